// round 16
// baseline (speedup 1.0000x reference)
#include <cuda_runtime.h>
#include <cuda_fp16.h>

// ImageNormalization2D: x (8,1024,1024,2) f32, k=61 box local std-normalization.
// R16: pB staging deleted — single CONTIGUOUS ownership ([8t,8t+8) per thread)
//   for loads, scans, window diffs and stores. v1/x go straight to registers,
//   "out" lives in registers between its window phase and the dual scan.
//   Smem = prefix buffers only (18.6 KB); 4 barriers (was 5); ~2.5k fewer
//   smem ops per row. pA/pC unchanged (measured plateaus).

#define NB 8
#define HB 1024
#define WB 1024
#define HALF_K 30
#define TOT (NB*HB*WB)       // channel-pair elements
#define CHUNK 8

#define NSEGA 16             // pass A segments
#define SEGROWSA (HB / NSEGA)
#define NSEGC 8              // pass C segments
#define SEGROWSC (HB / NSEGC)

static constexpr float SCALE_ = 1.0f / (61.0f * 61.0f * 2.0f);  // 1/(k*k*C)

// Scratch (static device globals; fp16x2 packed in unsigned)
__device__ unsigned g_v1[TOT];    // Vsum(x)                    32 MB
__device__ unsigned g_out[TOT];   // x - box(x)                 32 MB
__device__ uint2    g_u[TOT];     // {Hsum(out), Hsum(out^2)}   64 MB

#define PAD8(j) ((j) + ((j) >> 3))

static __device__ __forceinline__ float2 h2f(unsigned u) {
    __half2 h; *reinterpret_cast<unsigned*>(&h) = u;
    return __half22float2(h);
}
static __device__ __forceinline__ unsigned f2h(float a, float b) {
    __half2 h = __floats2half2_rn(a, b);
    return *reinterpret_cast<unsigned*>(&h);
}

// --------------- Pass A: vertical window sum of x -> v1 (fp16) -----------------
__global__ void __launch_bounds__(128) pA_vsum(const float2* __restrict__ x)
{
    const int g   = blockIdx.x * 128 + threadIdx.x;   // NB*WB*NSEGA threads
    const int w   = g & (WB - 1);
    const int nw  = g >> 10;
    const int n   = nw & (NB - 1);
    const int seg = nw >> 3;
    const int r0  = seg * SEGROWSA;
    const int base = (n * HB) * WB + w;

    // warm-up rows [r0-31, r0+29] (main loop subtracts r-31 BEFORE output at r)
    float sx = 0.f, sy = 0.f;
    #pragma unroll 6
    for (int j = 0; j <= 2 * HALF_K; ++j) {
        const int row = r0 - HALF_K - 1 + j;
        if (row >= 0) {
            float2 v = x[base + row * WB];
            sx += v.x; sy += v.y;
        }
    }

    float2 avA[CHUNK], svA[CHUNK], avB[CHUNK], svB[CHUNK];

    auto loadC = [&](int c, float2* av, float2* sv) {
        #pragma unroll
        for (int q = 0; q < CHUNK; ++q) {
            const int r   = r0 + c + q;
            const int add = r + HALF_K;
            const int sub = r - HALF_K - 1;
            av[q] = (add < HB) ? x[base + add * WB] : make_float2(0.f, 0.f);
            sv[q] = (sub >= 0) ? x[base + sub * WB] : make_float2(0.f, 0.f);
        }
    };
    auto compC = [&](int c, const float2* av, const float2* sv) {
        #pragma unroll
        for (int q = 0; q < CHUNK; ++q) {
            sx += av[q].x - sv[q].x; sy += av[q].y - sv[q].y;
            g_v1[base + (r0 + c + q) * WB] = f2h(sx, sy);
        }
    };

    loadC(0, avA, svA);
    #pragma unroll
    for (int c = 0; c < SEGROWSA; c += 2 * CHUNK) {
        loadC(c + CHUNK, avB, svB);
        compC(c, avA, svA);
        if (c + 2 * CHUNK < SEGROWSA)
            loadC(c + 2 * CHUNK, avA, svA);
        compC(c + CHUNK, avB, svB);
    }
}

// ------ Pass B: scan-based, zero-staging. One row per 128-thread block. --------
// Thread t owns pixels [8t, 8t+8) for everything. Smem = prefix buffers only.
__global__ void __launch_bounds__(128, 8) pB_hscan(const float4* __restrict__ x4)
{
    __shared__ float2 sPa[1160];     // P(v1), then P(out)   (PAD8: max idx 1150)
    __shared__ float2 sPb[1160];     // P(out^2)
    __shared__ float2 wsA[4];
    __shared__ float4 wsB[4];

    const int t    = threadIdx.x;       // 0..127
    const int lane = t & 31;
    const int wid  = t >> 5;
    const size_t base = (size_t)blockIdx.x * WB;

    // 1. load v1 span to regs (2x LDG.128 contiguous 32B... total 32B/thread)
    //    and scan -> sPa
    {
        const uint4* v4 = reinterpret_cast<const uint4*>(g_v1 + base) + 2 * t;
        uint4 a = v4[0], b = v4[1];
        unsigned vr[8] = {a.x, a.y, a.z, a.w, b.x, b.y, b.z, b.w};

        float2 pref[8];
        float ax = 0.f, ay = 0.f;
        #pragma unroll
        for (int q = 0; q < 8; ++q) {
            float2 v = h2f(vr[q]);
            ax += v.x; ay += v.y;
            pref[q] = make_float2(ax, ay);
        }
        float tx = ax, ty = ay;
        #pragma unroll
        for (int d = 1; d < 32; d <<= 1) {
            float ox = __shfl_up_sync(0xffffffffu, tx, d);
            float oy = __shfl_up_sync(0xffffffffu, ty, d);
            if (lane >= d) { tx += ox; ty += oy; }
        }
        if (lane == 31) wsA[wid] = make_float2(tx, ty);
        __syncthreads();
        float bx = tx - ax, by = ty - ay;           // exclusive within warp
        for (int k = 0; k < wid; ++k) { bx += wsA[k].x; by += wsA[k].y; }
        #pragma unroll
        for (int q = 0; q < 8; ++q)
            sPa[PAD8(8 * t + q)] = make_float2(bx + pref[q].x, by + pref[q].y);
    }
    __syncthreads();

    // 2. out = x - window(P1)*scale, straight from global x to registers.
    //    Keep fp16-rounded out in regs for the scans; store to g_out.
    float2 of[8];
    {
        const float4* xs = x4 + (size_t)blockIdx.x * (WB / 2) + 4 * t;
        float4 xr0 = xs[0], xr1 = xs[1], xr2 = xs[2], xr3 = xs[3];
        float xv[16] = {xr0.x, xr0.y, xr0.z, xr0.w, xr1.x, xr1.y, xr1.z, xr1.w,
                        xr2.x, xr2.y, xr2.z, xr2.w, xr3.x, xr3.y, xr3.z, xr3.w};
        unsigned orr[8];
        #pragma unroll
        for (int q = 0; q < 8; ++q) {
            const int w  = 8 * t + q;
            int hi = w + HALF_K; if (hi > WB - 1) hi = WB - 1;
            const int lo = w - HALF_K - 1;
            float2 m = sPa[PAD8(hi)];
            if (lo >= 0) { float2 p = sPa[PAD8(lo)]; m.x -= p.x; m.y -= p.y; }
            orr[q] = f2h(xv[2 * q] - m.x * SCALE_, xv[2 * q + 1] - m.y * SCALE_);
            of[q] = h2f(orr[q]);                    // fp16-rounded (matches g_out)
        }
        uint4* od = reinterpret_cast<uint4*>(g_out + base) + 2 * t;
        od[0] = make_uint4(orr[0], orr[1], orr[2], orr[3]);
        od[1] = make_uint4(orr[4], orr[5], orr[6], orr[7]);
    }

    // 3. dual scan of out, out^2 -> sPa, sPb (out already in regs)
    {
        float2 p1[8], p2[8];
        float a1x = 0.f, a1y = 0.f, a2x = 0.f, a2y = 0.f;
        #pragma unroll
        for (int q = 0; q < 8; ++q) {
            a1x += of[q].x;           a1y += of[q].y;
            a2x += of[q].x * of[q].x; a2y += of[q].y * of[q].y;
            p1[q] = make_float2(a1x, a1y);
            p2[q] = make_float2(a2x, a2y);
        }
        float t1x = a1x, t1y = a1y, t2x = a2x, t2y = a2y;
        #pragma unroll
        for (int d = 1; d < 32; d <<= 1) {
            float o1x = __shfl_up_sync(0xffffffffu, t1x, d);
            float o1y = __shfl_up_sync(0xffffffffu, t1y, d);
            float o2x = __shfl_up_sync(0xffffffffu, t2x, d);
            float o2y = __shfl_up_sync(0xffffffffu, t2y, d);
            if (lane >= d) { t1x += o1x; t1y += o1y; t2x += o2x; t2y += o2y; }
        }
        if (lane == 31) wsB[wid] = make_float4(t1x, t1y, t2x, t2y);
        __syncthreads();   // also guarantees all phase-2 sPa reads are done
        float b1x = t1x - a1x, b1y = t1y - a1y;
        float b2x = t2x - a2x, b2y = t2y - a2y;
        for (int k = 0; k < wid; ++k) {
            float4 s = wsB[k];
            b1x += s.x; b1y += s.y; b2x += s.z; b2y += s.w;
        }
        #pragma unroll
        for (int q = 0; q < 8; ++q) {
            sPa[PAD8(8 * t + q)] = make_float2(b1x + p1[q].x, b1y + p1[q].y);
            sPb[PAD8(8 * t + q)] = make_float2(b2x + p2[q].x, b2y + p2[q].y);
        }
    }
    __syncthreads();

    // 4. u windows -> g_u (4x STG.128 contiguous per thread)
    {
        uint2 ur[8];
        #pragma unroll
        for (int q = 0; q < 8; ++q) {
            const int w  = 8 * t + q;
            int hi = w + HALF_K; if (hi > WB - 1) hi = WB - 1;
            const int lo = w - HALF_K - 1;
            float2 u1 = sPa[PAD8(hi)], u2 = sPb[PAD8(hi)];
            if (lo >= 0) {
                float2 q1 = sPa[PAD8(lo)], q2 = sPb[PAD8(lo)];
                u1.x -= q1.x; u1.y -= q1.y; u2.x -= q2.x; u2.y -= q2.y;
            }
            ur[q] = make_uint2(f2h(u1.x, u1.y), f2h(u2.x, u2.y));
        }
        uint4* ud = reinterpret_cast<uint4*>(g_u + base) + 4 * t;
        ud[0] = make_uint4(ur[0].x, ur[0].y, ur[1].x, ur[1].y);
        ud[1] = make_uint4(ur[2].x, ur[2].y, ur[3].x, ur[3].y);
        ud[2] = make_uint4(ur[4].x, ur[4].y, ur[5].x, ur[5].y);
        ud[3] = make_uint4(ur[6].x, ur[6].y, ur[7].x, ur[7].y);
    }
}

// ------- Pass C: vertical sliding sums of u; result = out * rsqrt(var) ---------
__global__ void __launch_bounds__(128) pC_vpass(float2* __restrict__ res)
{
    const int g   = blockIdx.x * 128 + threadIdx.x;
    const int w   = g & (WB - 1);
    const int nw  = g >> 10;
    const int n   = nw & (NB - 1);
    const int seg = nw >> 3;
    const int r0  = seg * SEGROWSC;
    const int base = (n * HB) * WB + w;
    const uint2* __restrict__ u = g_u;

    // warm-up rows [r0-31, r0+29]
    float s1x = 0.f, s1y = 0.f, s2x = 0.f, s2y = 0.f;
    #pragma unroll 6
    for (int j = 0; j <= 2 * HALF_K; ++j) {
        const int row = r0 - HALF_K - 1 + j;
        if (row >= 0) {
            uint2 p = u[base + row * WB];
            float2 a = h2f(p.x), b = h2f(p.y);
            s1x += a.x; s1y += a.y; s2x += b.x; s2y += b.y;
        }
    }

    uint2    avA[CHUNK], svA[CHUNK], avB[CHUNK], svB[CHUNK];
    unsigned ovA[CHUNK], ovB[CHUNK];

    auto loadC = [&](int c, uint2* av, uint2* sv, unsigned* ov) {
        #pragma unroll
        for (int q = 0; q < CHUNK; ++q) {
            const int r   = r0 + c + q;
            const int add = r + HALF_K;
            const int sub = r - HALF_K - 1;
            av[q] = (add < HB) ? u[base + add * WB] : make_uint2(0u, 0u);
            sv[q] = (sub >= 0) ? u[base + sub * WB] : make_uint2(0u, 0u);
            ov[q] = g_out[base + r * WB];
        }
    };
    auto compC = [&](int c, const uint2* av, const uint2* sv, const unsigned* ov) {
        #pragma unroll
        for (int q = 0; q < CHUNK; ++q) {
            float2 a1 = h2f(av[q].x), a2 = h2f(av[q].y);
            float2 b1 = h2f(sv[q].x), b2 = h2f(sv[q].y);
            s1x += a1.x - b1.x; s1y += a1.y - b1.y;
            s2x += a2.x - b2.x; s2y += a2.y - b2.y;

            const float c1x = s1x * SCALE_, c1y = s1y * SCALE_;
            const float c2x = s2x * SCALE_, c2y = s2y * SCALE_;
            // 1/(sqrt(d)+1e-7) ~= rsqrt(d): rel diff ~1e-7 (std ~ 1 here)
            const float ix = rsqrtf(fmaxf(c2x - c1x * c1x, 1e-14f));
            const float iy = rsqrtf(fmaxf(c2y - c1y * c1y, 1e-14f));
            const float2 o = h2f(ov[q]);
            res[base + (c + q + r0) * WB] = make_float2(o.x * ix, o.y * iy);
        }
    };

    loadC(0, avA, svA, ovA);
    #pragma unroll
    for (int c = 0; c < SEGROWSC; c += 2 * CHUNK) {
        loadC(c + CHUNK, avB, svB, ovB);
        compC(c, avA, svA, ovA);
        if (c + 2 * CHUNK < SEGROWSC)
            loadC(c + 2 * CHUNK, avA, svA, ovA);
        compC(c + CHUNK, avB, svB, ovB);
    }
}

extern "C" void kernel_launch(void* const* d_in, const int* in_sizes, int n_in,
                              void* d_out, int out_size)
{
    (void)in_sizes; (void)n_in; (void)out_size;   // filter_size fixed at 61
    const float2* x = (const float2*)d_in[0];
    float2* res = (float2*)d_out;

    pA_vsum <<<(NB * WB * NSEGA) / 128, 128>>>(x);
    pB_hscan<<<NB * HB, 128>>>((const float4*)x);
    pC_vpass<<<(NB * WB * NSEGC) / 128, 128>>>(res);
}